// round 1
// baseline (speedup 1.0000x reference)
#include <cuda_runtime.h>
#include <cuda_bf16.h>
#include <cstdint>

// Problem constants
#define BB 4
#define CC 64
#define FF 64
#define TT 128
#define IC 32
#define NN (FF*TT)          // 8192
#define MM ((FF/2)*(TT/2))  // 2048

// Scratch (device globals; allocation is forbidden)
__device__ float  g_z[BB*CC*MM];          // z[b][o][m] = sum_i W[o,i]*psi[b,i,m]
__device__ float  g_q[BB*MM];             // q[b][m] = p_score - bpos
__device__ float  g_qs[BB*MM];            // sorted q
__device__ int    g_perm[BB*MM];          // sort permutation
__device__ float2 g_PQ[BB*(MM+1)*CC];     // PQ[b][k][o] = (P,Q) suffix sums

// ---------------------------------------------------------------------------
// K1: pooled psi/phi convs -> q[b,m], z[b,o,m]
// grid 512 (= B * M/16), block 128
// ---------------------------------------------------------------------------
__global__ __launch_bounds__(128) void k1_zq(
    const float* __restrict__ x,
    const float* __restrict__ psi_w, const float* __restrict__ psi_b,
    const float* __restrict__ phi_w, const float* __restrict__ phi_b,
    const float* __restrict__ h1_w,  const float* __restrict__ h2_w,
    const float* __restrict__ W_w)
{
    __shared__ __align__(16) float xs[64*2*32];   // [c][row][tl]
    __shared__ float wps[64*33];                  // psi_w transposed [c][i], padded
    __shared__ float wph[64*33];
    __shared__ float Wws[64*33];                  // W_w as-is [o][i], 33 = IC+1
    __shared__ float psi_s[16*33];
    __shared__ float phi_s[16*33];

    int tid = threadIdx.x;
    int bid = blockIdx.x;
    int b = bid >> 7;
    int mbase = (bid & 127) << 4;    // 16 m's, all same fm
    int fm = mbase >> 6;
    int tm0 = mbase & 63;

    const float* xb = x + (size_t)b*CC*NN;
    // load x tile: channels x 2 rows x 32 t
    for (int u = tid; u < 4096; u += 128) {
        int c = u >> 6; int rem = u & 63; int r = rem >> 5; int tl = rem & 31;
        xs[u] = xb[(c*FF + 2*fm + r)*TT + 2*tm0 + tl];
    }
    // stage weights (psi/phi transposed with pad 33, W as-is)
    for (int u = tid; u < 2048; u += 128) {
        int i = u >> 6; int c = u & 63;
        wps[c*33+i] = psi_w[u];
        wph[c*33+i] = phi_w[u];
    }
    for (int u = tid; u < 2112; u += 128) Wws[u] = W_w[u];
    __syncthreads();

    // pooled conv: tasks (ml 0..15, i 0..31)
    #pragma unroll
    for (int rep = 0; rep < 4; rep++) {
        int tt = rep*128 + tid;
        int ml = tt >> 5, i = tt & 31;
        float p0=0,p1=0,p2=0,p3=0,f0=0,f1=0,f2=0,f3=0;
        #pragma unroll 8
        for (int c = 0; c < 64; c++) {
            float wpsv = wps[c*33+i];
            float wphv = wph[c*33+i];
            float2 v0 = *(const float2*)&xs[(c*2+0)*32 + 2*ml];
            float2 v1 = *(const float2*)&xs[(c*2+1)*32 + 2*ml];
            p0 += wpsv*v0.x; p1 += wpsv*v0.y; p2 += wpsv*v1.x; p3 += wpsv*v1.y;
            f0 += wphv*v0.x; f1 += wphv*v0.y; f2 += wphv*v1.x; f3 += wphv*v1.y;
        }
        psi_s[ml*33+i] = fmaxf(fmaxf(p0,p1),fmaxf(p2,p3)) + psi_b[i];
        phi_s[ml*33+i] = fmaxf(fmaxf(f0,f1),fmaxf(f2,f3)) + phi_b[i];
    }
    __syncthreads();

    // q[b,m]
    if (tid < 16) {
        int m = mbase + tid;
        float acc = 0.f;
        #pragma unroll
        for (int i = 0; i < 32; i++) acc += h1_w[i]*phi_s[tid*33+i];
        int fmm = m >> 6, tmm = m & 63;
        float bp = h2_w[0]*(fmm*(1.0f/31.0f)) + h2_w[1]*(tmm*(1.0f/63.0f));
        g_q[b*MM + m] = acc - bp;
    }

    // z[b,o,m] = sum_i W[o,i]*psi[i,m]
    #pragma unroll
    for (int rep = 0; rep < 8; rep++) {
        int tt = rep*128 + tid;
        int o = tt >> 4, ml = tt & 15;
        float acc = 0.f;
        #pragma unroll
        for (int i = 0; i < 32; i++) acc += Wws[o*33+i]*psi_s[ml*33+i];
        g_z[((size_t)b*CC + o)*MM + mbase + ml] = acc;
    }
}

// ---------------------------------------------------------------------------
// K2: per-batch bitonic sort of q (ascending), with permutation
// grid 4, block 1024
// ---------------------------------------------------------------------------
__global__ __launch_bounds__(1024) void k2_sort()
{
    __shared__ float key[MM];
    __shared__ int   idx[MM];
    int b = blockIdx.x;
    int t = threadIdx.x;
    for (int i = t; i < MM; i += 1024) { key[i] = g_q[b*MM+i]; idx[i] = i; }
    __syncthreads();
    for (int k = 2; k <= MM; k <<= 1) {
        for (int j = k >> 1; j > 0; j >>= 1) {
            for (int i = t; i < MM; i += 1024) {
                int ixj = i ^ j;
                if (ixj > i) {
                    bool up = ((i & k) == 0);
                    float a = key[i], c2 = key[ixj];
                    if ((a > c2) == up) {
                        key[i] = c2; key[ixj] = a;
                        int tmp = idx[i]; idx[i] = idx[ixj]; idx[ixj] = tmp;
                    }
                }
            }
            __syncthreads();
        }
    }
    for (int i = t; i < MM; i += 1024) {
        g_qs[b*MM+i] = key[i];
        g_perm[b*MM+i] = idx[i];
    }
}

// ---------------------------------------------------------------------------
// K3: suffix sums P[k]=sum_{j>=k} z[perm[j]], Q[k]=sum_{j>=k} qs[j]*z[perm[j]]
// Output layout PQ[b][k][o] for contiguous per-n reads in K4.
// grid 256 (= B*C), block 256
// ---------------------------------------------------------------------------
__global__ __launch_bounds__(256) void k3_scan()
{
    __shared__ float zS[MM];
    __shared__ float qsS[MM];
    __shared__ int   pS[MM];
    __shared__ float tp[256], tq[256];

    int bo = blockIdx.x;
    int b = bo >> 6, o = bo & 63;
    int t = threadIdx.x;

    const float* zrow = g_z + ((size_t)b*CC + o)*MM;
    for (int i = t; i < MM; i += 256) {
        zS[i]  = zrow[i];
        qsS[i] = g_qs[b*MM+i];
        pS[i]  = g_perm[b*MM+i];
    }
    __syncthreads();

    float vP[8], vQ[8];
    int base = t*8;
    float sp = 0.f, sq = 0.f;
    #pragma unroll
    for (int e = 7; e >= 0; e--) {
        float zv = zS[pS[base+e]];
        sp += zv;
        sq += qsS[base+e]*zv;
        vP[e] = sp; vQ[e] = sq;
    }
    tp[t] = sp; tq[t] = sq;
    __syncthreads();
    for (int d = 1; d < 256; d <<= 1) {
        float ap = (t + d < 256) ? tp[t+d] : 0.f;
        float aq = (t + d < 256) ? tq[t+d] : 0.f;
        __syncthreads();
        tp[t] += ap; tq[t] += aq;
        __syncthreads();
    }
    float offP = (t < 255) ? tp[t+1] : 0.f;
    float offQ = (t < 255) ? tq[t+1] : 0.f;

    float2* out = g_PQ + (size_t)b*(MM+1)*CC;
    #pragma unroll
    for (int e = 0; e < 8; e++)
        out[(size_t)(base+e)*CC + o] = make_float2(vP[e]+offP, vQ[e]+offQ);
    if (t == 0) out[(size_t)MM*CC + o] = make_float2(0.f, 0.f);
}

// ---------------------------------------------------------------------------
// K4: s_n + binary search + apply suffix sums + BN + residual
// grid 256 (= B * N/128), block 128
// ---------------------------------------------------------------------------
__global__ __launch_bounds__(128) void k4_apply(
    const float* __restrict__ x,
    const float* __restrict__ theta_w, const float* __restrict__ theta_b,
    const float* __restrict__ h0_w,    const float* __restrict__ h2_w,
    const float* __restrict__ W_b,
    const float* __restrict__ bn_g, const float* __restrict__ bn_b,
    const float* __restrict__ bn_m, const float* __restrict__ bn_v,
    float* __restrict__ out)
{
    __shared__ float qsS[MM];
    __shared__ float uS[64];
    __shared__ float As[64], Ds[64];
    __shared__ float ss[128];
    __shared__ int   kk[128];
    __shared__ float tile[64*129];
    __shared__ float tbS;

    int tid = threadIdx.x;
    int bid = blockIdx.x;
    int b = bid >> 6;
    int nbase = (bid & 63) << 7;

    for (int i = tid; i < MM; i += 128) qsS[i] = g_qs[b*MM+i];
    if (tid < 64) {
        float acc = 0.f;
        #pragma unroll
        for (int i = 0; i < 32; i++) acc += h0_w[i]*theta_w[i*64+tid];
        uS[tid] = acc;
        float inv = bn_g[tid]*rsqrtf(bn_v[tid] + 1e-5f);
        As[tid] = inv*(1.0f/(float)MM);
        Ds[tid] = W_b[tid]*inv + bn_b[tid] - bn_m[tid]*inv;
    } else if (tid == 64) {
        float acc = 0.f;
        #pragma unroll
        for (int i = 0; i < 32; i++) acc += h0_w[i]*theta_b[i];
        tbS = acc;
    }
    __syncthreads();

    int n = nbase + tid;
    const float* xb = x + (size_t)b*CC*NN;
    float s = tbS;
    #pragma unroll 8
    for (int c = 0; c < 64; c++) s += uS[c]*xb[c*NN + n];
    int f_ = n >> 7, t_ = n & 127;
    s += h2_w[0]*(f_*(1.0f/63.0f)) + h2_w[1]*(t_*(1.0f/127.0f));

    // first index with qs[k] > -s  (active set = k..M-1)
    float keyv = -s;
    int lo = 0, hi = MM;
    while (lo < hi) {
        int mid = (lo + hi) >> 1;
        if (qsS[mid] > keyv) hi = mid; else lo = mid + 1;
    }
    ss[tid] = s; kk[tid] = lo;
    __syncthreads();

    int w = tid >> 5, lane = tid & 31;
    const float2* PQ = g_PQ + (size_t)b*(MM+1)*CC;
    #pragma unroll 4
    for (int j = 0; j < 32; j++) {
        int jj = w*32 + j;
        float sv = ss[jj];
        int k = kk[jj];
        float2 a0 = PQ[(size_t)k*CC + lane];
        float2 a1 = PQ[(size_t)k*CC + 32 + lane];
        tile[lane*129 + jj]      = sv*a0.x + a0.y;
        tile[(lane+32)*129 + jj] = sv*a1.x + a1.y;
    }
    __syncthreads();

    float* ob = out + (size_t)b*CC*NN;
    #pragma unroll 4
    for (int o = 0; o < 64; o++) {
        int oidx = o*NN + nbase + tid;
        ob[oidx] = tile[o*129 + tid]*As[o] + Ds[o] + xb[oidx];
    }
}

// ---------------------------------------------------------------------------
extern "C" void kernel_launch(void* const* d_in, const int* in_sizes, int n_in,
                              void* d_out, int out_size)
{
    const float* x       = (const float*)d_in[0];
    const float* psi_w   = (const float*)d_in[1];
    const float* psi_b   = (const float*)d_in[2];
    const float* theta_w = (const float*)d_in[3];
    const float* theta_b = (const float*)d_in[4];
    const float* phi_w   = (const float*)d_in[5];
    const float* phi_b   = (const float*)d_in[6];
    const float* h0_w    = (const float*)d_in[7];
    const float* h1_w    = (const float*)d_in[8];
    const float* h2_w    = (const float*)d_in[9];
    const float* W_w     = (const float*)d_in[10];
    const float* W_b     = (const float*)d_in[11];
    const float* bn_g    = (const float*)d_in[12];
    const float* bn_b    = (const float*)d_in[13];
    const float* bn_m    = (const float*)d_in[14];
    const float* bn_v    = (const float*)d_in[15];
    float* out = (float*)d_out;

    k1_zq<<<512, 128>>>(x, psi_w, psi_b, phi_w, phi_b, h1_w, h2_w, W_w);
    k2_sort<<<4, 1024>>>();
    k3_scan<<<256, 256>>>();
    k4_apply<<<256, 128>>>(x, theta_w, theta_b, h0_w, h2_w, W_b,
                           bn_g, bn_b, bn_m, bn_v, out);
}

// round 2
// speedup vs baseline: 1.1600x; 1.1600x over previous
#include <cuda_runtime.h>
#include <cuda_bf16.h>
#include <cstdint>

#define BB 4
#define CC 64
#define FF 64
#define TT 128
#define IC 32
#define NN 8192
#define MM 2048
#define EPSF 1e-5f

// Scratch (device globals; allocation forbidden)
__device__ float  g_q[BB*MM];
__device__ float  g_qs[BB*MM];
__device__ int    g_perm[BB*MM];
__device__ float  g_z[BB*CC*MM];
__device__ float  g_s[BB*NN];
__device__ int    g_k[BB*NN];
__device__ float2 g_PQ[BB*(MM+1)*CC];

__device__ __forceinline__ void ffma2(unsigned long long &d, unsigned long long a, unsigned long long b) {
    asm("fma.rn.f32x2 %0, %1, %2, %0;" : "+l"(d) : "l"(a), "l"(b));
}
__device__ __forceinline__ unsigned long long dup2(float v) {
    unsigned long long r; asm("mov.b64 %0, {%1, %1};" : "=l"(r) : "f"(v)); return r;
}
__device__ __forceinline__ float2 unpk(unsigned long long v) {
    float2 r; asm("mov.b64 {%0, %1}, %2;" : "=f"(r.x), "=f"(r.y) : "l"(v)); return r;
}

// ---------------------------------------------------------------------------
// K1: pooled psi/phi convs -> q[b,m], z[b,o,m]; also s[b,n] (theta folded).
// grid 256 (= B * 64 m-groups of 32), block 128, dynamic smem 65540B.
// Register-blocked FFMA2 conv: 8 i x 4 pool positions per thread per conv.
// ---------------------------------------------------------------------------
__global__ __launch_bounds__(128) void k1_zq(
    const float* __restrict__ x,
    const float* __restrict__ psi_w, const float* __restrict__ psi_b,
    const float* __restrict__ theta_w, const float* __restrict__ theta_b,
    const float* __restrict__ phi_w, const float* __restrict__ phi_b,
    const float* __restrict__ h0_w, const float* __restrict__ h1_w,
    const float* __restrict__ h2_w, const float* __restrict__ W_w)
{
    extern __shared__ float dsm[];
    float*  xs      = dsm;                       // [c][r][tl] 64*2*64 = 8192
    float2* wpsp    = (float2*)(dsm + 8192);     // [c][18] pairs (i, i+16)
    float2* wphp    = (float2*)(dsm + 10496);
    float2* Wwsp    = (float2*)(dsm + 12800);    // [o][18] pairs
    float2* psi_sp  = (float2*)(dsm + 15104);    // [ml][17] pairs
    float*  phi_part= dsm + 16192;               // [ml][4]
    float*  uS      = dsm + 16320;               // [64]
    float*  tbS     = dsm + 16384;               // [1]

    int tid = threadIdx.x;
    int bid = blockIdx.x;
    int b  = bid >> 6;
    int g  = bid & 63;
    int fm = g >> 1;
    int tm0 = (g & 1) << 5;
    int f0 = fm << 1;
    int t0 = tm0 << 1;

    const float* xb = x + (size_t)b*CC*NN;
    for (int u = tid; u < 8192; u += 128) {
        int cc = u >> 7, rem = u & 127;
        xs[u] = xb[(size_t)(cc*FF + f0 + (rem >> 6))*TT + t0 + (rem & 63)];
    }
    for (int u = tid; u < 1024; u += 128) {
        int it = u >> 6, cc = u & 63;
        wpsp[cc*18 + it] = make_float2(psi_w[it*CC + cc], psi_w[(it+16)*CC + cc]);
        wphp[cc*18 + it] = make_float2(phi_w[it*CC + cc], phi_w[(it+16)*CC + cc]);
    }
    for (int u = tid; u < 1024; u += 128) {
        int o = u >> 4, it = u & 15;
        Wwsp[o*18 + it] = make_float2(W_w[o*33 + it], W_w[o*33 + it + 16]);
    }
    if (tid < 64) {
        float acc = 0.f;
        #pragma unroll
        for (int i = 0; i < 32; i++) acc = fmaf(h0_w[i], theta_w[i*CC + tid], acc);
        uS[tid] = acc;
    } else if (tid == 64) {
        float acc = 0.f;
        #pragma unroll
        for (int i = 0; i < 32; i++) acc = fmaf(h0_w[i], theta_b[i], acc);
        *tbS = acc;
    }
    __syncthreads();

    // ---- register-blocked pooled conv ----
    int ml = tid >> 2, ig = tid & 3;            // ml 0..31, ig 0..3 (it0 = ig*4)
    unsigned long long ap[16], af[16];
    #pragma unroll
    for (int i = 0; i < 16; i++) { ap[i] = 0ull; af[i] = 0ull; }
    const float2* wp0 = wpsp + ig*4;
    const float2* wf0 = wphp + ig*4;
    const float*  xrow = xs + 2*ml;
    #pragma unroll 8
    for (int cc = 0; cc < 64; cc++) {
        ulonglong2 wPa = *(const ulonglong2*)(wp0 + cc*18);
        ulonglong2 wPb = *(const ulonglong2*)(wp0 + cc*18 + 2);
        ulonglong2 wFa = *(const ulonglong2*)(wf0 + cc*18);
        ulonglong2 wFb = *(const ulonglong2*)(wf0 + cc*18 + 2);
        float2 v0 = *(const float2*)(xrow + cc*128);
        float2 v1 = *(const float2*)(xrow + cc*128 + 64);
        unsigned long long d00 = dup2(v0.x), d01 = dup2(v0.y);
        unsigned long long d10 = dup2(v1.x), d11 = dup2(v1.y);
        ffma2(ap[ 0], wPa.x, d00); ffma2(ap[ 1], wPa.x, d01); ffma2(ap[ 2], wPa.x, d10); ffma2(ap[ 3], wPa.x, d11);
        ffma2(ap[ 4], wPa.y, d00); ffma2(ap[ 5], wPa.y, d01); ffma2(ap[ 6], wPa.y, d10); ffma2(ap[ 7], wPa.y, d11);
        ffma2(ap[ 8], wPb.x, d00); ffma2(ap[ 9], wPb.x, d01); ffma2(ap[10], wPb.x, d10); ffma2(ap[11], wPb.x, d11);
        ffma2(ap[12], wPb.y, d00); ffma2(ap[13], wPb.y, d01); ffma2(ap[14], wPb.y, d10); ffma2(ap[15], wPb.y, d11);
        ffma2(af[ 0], wFa.x, d00); ffma2(af[ 1], wFa.x, d01); ffma2(af[ 2], wFa.x, d10); ffma2(af[ 3], wFa.x, d11);
        ffma2(af[ 4], wFa.y, d00); ffma2(af[ 5], wFa.y, d01); ffma2(af[ 6], wFa.y, d10); ffma2(af[ 7], wFa.y, d11);
        ffma2(af[ 8], wFb.x, d00); ffma2(af[ 9], wFb.x, d01); ffma2(af[10], wFb.x, d10); ffma2(af[11], wFb.x, d11);
        ffma2(af[12], wFb.y, d00); ffma2(af[13], wFb.y, d01); ffma2(af[14], wFb.y, d10); ffma2(af[15], wFb.y, d11);
    }

    // pool (max over 4 positions) + bias; psi pairs to smem, phi -> partial q
    float qpart = 0.f;
    #pragma unroll
    for (int qd = 0; qd < 4; qd++) {
        int i_lo = ig*4 + qd, i_hi = i_lo + 16;
        float2 p0 = unpk(ap[qd*4+0]), p1 = unpk(ap[qd*4+1]);
        float2 p2 = unpk(ap[qd*4+2]), p3 = unpk(ap[qd*4+3]);
        float plo = fmaxf(fmaxf(p0.x,p1.x), fmaxf(p2.x,p3.x)) + psi_b[i_lo];
        float phv = fmaxf(fmaxf(p0.y,p1.y), fmaxf(p2.y,p3.y)) + psi_b[i_hi];
        psi_sp[ml*17 + i_lo] = make_float2(plo, phv);
        float2 q0 = unpk(af[qd*4+0]), q1 = unpk(af[qd*4+1]);
        float2 q2 = unpk(af[qd*4+2]), q3 = unpk(af[qd*4+3]);
        float flo = fmaxf(fmaxf(q0.x,q1.x), fmaxf(q2.x,q3.x)) + phi_b[i_lo];
        float fhi = fmaxf(fmaxf(q0.y,q1.y), fmaxf(q2.y,q3.y)) + phi_b[i_hi];
        qpart = fmaf(h1_w[i_lo], flo, qpart);
        qpart = fmaf(h1_w[i_hi], fhi, qpart);
    }
    phi_part[ml*4 + ig] = qpart;

    // s[n] for the 128 n's this tile covers (uses resident xs)
    {
        int r_ = tid >> 6, tl = tid & 63;
        const float* xr = xs + r_*64 + tl;
        float s = *tbS;
        #pragma unroll 16
        for (int cc = 0; cc < 64; cc++) s = fmaf(uS[cc], xr[cc*128], s);
        int fg = f0 + r_, tg = t0 + tl;
        s += h2_w[0]*((float)fg*(1.f/63.f)) + h2_w[1]*((float)tg*(1.f/127.f));
        g_s[b*NN + fg*TT + tg] = s;
    }
    __syncthreads();

    if (tid < 32) {
        float acc = phi_part[tid*4] + phi_part[tid*4+1] + phi_part[tid*4+2] + phi_part[tid*4+3];
        int tmm = tm0 + tid;
        float bp = h2_w[0]*((float)fm*(1.f/31.f)) + h2_w[1]*((float)tmm*(1.f/63.f));
        g_q[b*MM + fm*64 + tmm] = acc - bp;
    }

    // z[o][m] = sum_i W[o,i]*psi[i,m]  (FFMA2 over 16 i-pairs)
    const unsigned long long* Ww64 = (const unsigned long long*)Wwsp;
    const unsigned long long* Ps64 = (const unsigned long long*)psi_sp;
    float* zout = g_z + (size_t)b*CC*MM + fm*64 + tm0;
    #pragma unroll 4
    for (int rep = 0; rep < 16; rep++) {
        int task = rep*128 + tid;
        int o = task >> 5, mlz = task & 31;
        unsigned long long acc = 0ull;
        #pragma unroll
        for (int it = 0; it < 16; it++)
            ffma2(acc, Ww64[o*18 + it], Ps64[mlz*17 + it]);
        float2 rr = unpk(acc);
        zout[(size_t)o*MM + mlz] = rr.x + rr.y;
    }
}

// ---------------------------------------------------------------------------
// K2: per-batch bitonic sort of q (register/shfl for j<=32, smem for j>=64),
// then all N binary searches for this batch. grid 4, block 1024.
// Elements packed u64: (order-preserving key << 32) | index.
// ---------------------------------------------------------------------------
__global__ __launch_bounds__(1024) void k2_sort_search()
{
    __shared__ unsigned long long sm[MM];
    __shared__ float keyF[MM];
    int b = blockIdx.x;
    int t = threadIdx.x;
    int lane = t & 31;
    int e0 = (t >> 5)*64 + lane*2;
    int e1 = e0 + 1;

    float2 f01 = *(const float2*)(g_q + b*MM + e0);
    unsigned u0 = __float_as_uint(f01.x); u0 ^= ((int)u0 < 0 ? 0xFFFFFFFFu : 0x80000000u);
    unsigned u1 = __float_as_uint(f01.y); u1 ^= ((int)u1 < 0 ? 0xFFFFFFFFu : 0x80000000u);
    unsigned long long a = ((unsigned long long)u0 << 32) | (unsigned)e0;
    unsigned long long c = ((unsigned long long)u1 << 32) | (unsigned)e1;

    #pragma unroll 1
    for (int k = 2; k <= MM; k <<= 1) {
        #pragma unroll 1
        for (int j = k >> 1; j > 0; j >>= 1) {
            if (j >= 64) {
                __syncthreads();
                sm[e0] = a; sm[e1] = c;
                __syncthreads();
                unsigned long long pa = sm[e0 ^ j];
                unsigned long long pc = sm[e1 ^ j];
                bool keepmin = (((e0 & j) == 0) == ((e0 & k) == 0));
                a = keepmin ? (a < pa ? a : pa) : (a < pa ? pa : a);
                c = keepmin ? (c < pc ? c : pc) : (c < pc ? pc : c);
            } else if (j >= 2) {
                int msk = j >> 1;
                unsigned long long pa = __shfl_xor_sync(0xFFFFFFFFu, a, msk);
                unsigned long long pc = __shfl_xor_sync(0xFFFFFFFFu, c, msk);
                bool keepmin = (((lane & msk) == 0) == ((e0 & k) == 0));
                a = keepmin ? (a < pa ? a : pa) : (a < pa ? pa : a);
                c = keepmin ? (c < pc ? c : pc) : (c < pc ? pc : c);
            } else {
                bool up = ((e0 & k) == 0);
                unsigned long long mn = (a < c ? a : c), mx = (a < c ? c : a);
                a = up ? mn : mx;
                c = up ? mx : mn;
            }
        }
    }
    {
        unsigned k0 = (unsigned)(a >> 32); k0 ^= ((int)k0 < 0 ? 0x80000000u : 0xFFFFFFFFu);
        unsigned k1v = (unsigned)(c >> 32); k1v ^= ((int)k1v < 0 ? 0x80000000u : 0xFFFFFFFFu);
        float fa = __uint_as_float(k0), fc = __uint_as_float(k1v);
        keyF[e0] = fa; keyF[e1] = fc;
        g_qs[b*MM + e0] = fa; g_qs[b*MM + e1] = fc;
        g_perm[b*MM + e0] = (int)(unsigned)(a & 0xFFFFFFFFull);
        g_perm[b*MM + e1] = (int)(unsigned)(c & 0xFFFFFFFFull);
    }
    __syncthreads();

    // binary searches: first k with qs[k] > -s[n]
    #pragma unroll
    for (int r = 0; r < 8; r++) {
        int n = r*1024 + t;
        float keyv = -g_s[b*NN + n];
        int lo = 0, hi = MM;
        while (lo < hi) { int mid = (lo + hi) >> 1; if (keyF[mid] > keyv) hi = mid; else lo = mid + 1; }
        g_k[b*NN + n] = lo;
    }
}

// ---------------------------------------------------------------------------
// K3: suffix sums over sorted order, pre-scaled by As[o] = inv[o]/M.
// grid 256 (= B*C), block 256. Warp-shuffle suffix scan (2 barriers).
// ---------------------------------------------------------------------------
__global__ __launch_bounds__(256) void k3_scan(
    const float* __restrict__ bn_g, const float* __restrict__ bn_v)
{
    __shared__ float zS[MM];
    __shared__ float qsS[MM];
    __shared__ int   pS[MM];
    __shared__ float wtP[8], wtQ[8];

    int bo = blockIdx.x;
    int b = bo >> 6, o = bo & 63;
    int t = threadIdx.x, lane = t & 31, w = t >> 5;

    const float* zrow = g_z + ((size_t)b*CC + o)*MM;
    for (int i = t; i < MM; i += 256) {
        zS[i] = zrow[i]; qsS[i] = g_qs[b*MM + i]; pS[i] = g_perm[b*MM + i];
    }
    __syncthreads();

    float vP[8], vQ[8];
    int base = t*8;
    float sp = 0.f, sq = 0.f;
    #pragma unroll
    for (int e = 7; e >= 0; e--) {
        float zv = zS[pS[base + e]];
        sp += zv; sq = fmaf(qsS[base + e], zv, sq);
        vP[e] = sp; vQ[e] = sq;
    }
    float isp = sp, isq = sq;
    #pragma unroll
    for (int d = 1; d < 32; d <<= 1) {
        float tp = __shfl_down_sync(0xFFFFFFFFu, isp, d);
        float tq = __shfl_down_sync(0xFFFFFFFFu, isq, d);
        if (lane + d < 32) { isp += tp; isq += tq; }
    }
    if (lane == 0) { wtP[w] = isp; wtQ[w] = isq; }
    __syncthreads();
    float offP = isp - sp, offQ = isq - sq;
    #pragma unroll
    for (int w2 = 0; w2 < 8; w2++) if (w2 > w) { offP += wtP[w2]; offQ += wtQ[w2]; }

    float As = bn_g[o]*rsqrtf(bn_v[o] + EPSF)*(1.0f/(float)MM);
    float2* outp = g_PQ + (size_t)b*(MM+1)*CC;
    #pragma unroll
    for (int e = 0; e < 8; e++)
        outp[(size_t)(base + e)*CC + o] = make_float2((vP[e]+offP)*As, (vQ[e]+offQ)*As);
    if (t == 0) outp[(size_t)MM*CC + o] = make_float2(0.f, 0.f);
}

// ---------------------------------------------------------------------------
// K4: gather PQ rows + transpose + BN offset + residual.
// grid 1024 (= B * 128 n-groups * 2 o-halves), block 128.
// ---------------------------------------------------------------------------
__global__ __launch_bounds__(128) void k4_apply(
    const float* __restrict__ x, const float* __restrict__ W_b,
    const float* __restrict__ bn_g, const float* __restrict__ bn_b,
    const float* __restrict__ bn_m, const float* __restrict__ bn_v,
    float* __restrict__ out)
{
    __shared__ float tile[32*65];
    __shared__ float ssS[64];
    __shared__ int   kkS[64];
    __shared__ float DsS[32];

    int tid = threadIdx.x;
    int bid = blockIdx.x;
    int b = bid >> 8;
    int r = bid & 255;
    int ng = r >> 1, half = r & 1;
    int nbase = ng << 6;

    if (tid < 64) ssS[tid] = g_s[b*NN + nbase + tid];
    else          kkS[tid - 64] = g_k[b*NN + nbase + tid - 64];
    if (tid < 32) {
        int o = half*32 + tid;
        float inv = bn_g[o]*rsqrtf(bn_v[o] + EPSF);
        DsS[tid] = fmaf(W_b[o], inv, bn_b[o] - bn_m[o]*inv);
    }
    __syncthreads();

    int w = tid >> 5, lane = tid & 31;
    const float2* PQ = g_PQ + (size_t)b*(MM+1)*CC + half*32;
    #pragma unroll
    for (int qd = 0; qd < 16; qd++) {
        int jj = w*16 + qd;
        float sv = ssS[jj];
        int k = kkS[jj];
        float2 av = PQ[(size_t)k*CC + lane];
        tile[lane*65 + jj] = fmaf(sv, av.x, av.y);
    }
    __syncthreads();

    const float* xb = x   + ((size_t)b*CC + half*32)*NN;
    float*       ob = out + ((size_t)b*CC + half*32)*NN;
    int nl = tid & 63, oh = tid >> 6;
    #pragma unroll
    for (int rep = 0; rep < 16; rep++) {
        int ol = rep*2 + oh;
        size_t idx = (size_t)ol*NN + nbase + nl;
        ob[idx] = tile[ol*65 + nl] + DsS[ol] + xb[idx];
    }
}

// ---------------------------------------------------------------------------
extern "C" void kernel_launch(void* const* d_in, const int* in_sizes, int n_in,
                              void* d_out, int out_size)
{
    const float* x       = (const float*)d_in[0];
    const float* psi_w   = (const float*)d_in[1];
    const float* psi_b   = (const float*)d_in[2];
    const float* theta_w = (const float*)d_in[3];
    const float* theta_b = (const float*)d_in[4];
    const float* phi_w   = (const float*)d_in[5];
    const float* phi_b   = (const float*)d_in[6];
    const float* h0_w    = (const float*)d_in[7];
    const float* h1_w    = (const float*)d_in[8];
    const float* h2_w    = (const float*)d_in[9];
    const float* W_w     = (const float*)d_in[10];
    const float* W_b     = (const float*)d_in[11];
    const float* bn_g    = (const float*)d_in[12];
    const float* bn_b    = (const float*)d_in[13];
    const float* bn_m    = (const float*)d_in[14];
    const float* bn_v    = (const float*)d_in[15];
    float* out = (float*)d_out;

    cudaFuncSetAttribute(k1_zq, cudaFuncAttributeMaxDynamicSharedMemorySize, 65540);
    k1_zq<<<256, 128, 65540>>>(x, psi_w, psi_b, theta_w, theta_b, phi_w, phi_b,
                               h0_w, h1_w, h2_w, W_w);
    k2_sort_search<<<4, 1024>>>();
    k3_scan<<<256, 256>>>(bn_g, bn_v);
    k4_apply<<<1024, 128>>>(x, W_b, bn_g, bn_b, bn_m, bn_v, out);
}

// round 7
// speedup vs baseline: 1.3677x; 1.1791x over previous
#include <cuda_runtime.h>
#include <cuda_bf16.h>
#include <cstdint>

#define BB 4
#define CC 64
#define FF 64
#define TT 128
#define IC 32
#define NN 8192
#define MM 2048
#define EPSF 1e-5f

// Scratch (device globals; allocation forbidden)
__device__ float  g_q[BB*MM];
__device__ float  g_qs[BB*MM];
__device__ int    g_perm[BB*MM];
__device__ float  g_z[BB*CC*MM];
__device__ float  g_s[BB*NN];
__device__ int    g_k[BB*NN];
__device__ float2 g_PQ[BB*CC*(MM+1)];   // [b][o][k]: (P,Q) suffix sums, pre-scaled

__device__ __forceinline__ void ffma2(unsigned long long &d, unsigned long long a, unsigned long long b) {
    asm("fma.rn.f32x2 %0, %1, %2, %0;" : "+l"(d) : "l"(a), "l"(b));
}
__device__ __forceinline__ unsigned long long dup2(float v) {
    unsigned long long r; asm("mov.b64 %0, {%1, %1};" : "=l"(r) : "f"(v)); return r;
}
__device__ __forceinline__ float2 unpk(unsigned long long v) {
    float2 r; asm("mov.b64 {%0, %1}, %2;" : "=f"(r.x), "=f"(r.y) : "l"(v)); return r;
}

// ---------------------------------------------------------------------------
// K1: pooled psi/phi convs -> q[b,m], z[b,o,m]; also s[b,n] (theta folded).
// grid 512 (= B * 128 tiles of 16 m), block 128, static smem ~45KB.
// ---------------------------------------------------------------------------
__global__ __launch_bounds__(128) void k1_zq(
    const float* __restrict__ x,
    const float* __restrict__ psi_w, const float* __restrict__ psi_b,
    const float* __restrict__ theta_w, const float* __restrict__ theta_b,
    const float* __restrict__ phi_w, const float* __restrict__ phi_b,
    const float* __restrict__ h0_w, const float* __restrict__ h1_w,
    const float* __restrict__ h2_w, const float* __restrict__ W_w)
{
    __shared__ __align__(16) float  xs[64*2*32];       // [c][r][tl]
    __shared__ __align__(16) float2 wpsp[64*18];       // [c][j] pairs (j, j+16)
    __shared__ __align__(16) float2 wphp[64*18];
    __shared__ __align__(16) float2 Wwsp[64*18];       // [o][j] pairs
    __shared__ __align__(16) float2 psi_sp[16*17];     // [ml][j] pairs
    __shared__ float phi_part[16*8];
    __shared__ float uS[64];
    __shared__ float tbS;

    int tid = threadIdx.x;
    int bid = blockIdx.x;
    int b   = bid >> 7;
    int g   = bid & 127;
    int fm  = g >> 2;
    int tm0 = (g & 3) << 4;
    int f0 = fm << 1;
    int t0 = tm0 << 1;

    const float* xb = x + (size_t)b*CC*NN;
    #pragma unroll
    for (int rep = 0; rep < 32; rep++) {
        int u = rep*128 + tid;
        int cc = u >> 6, r = (u >> 5) & 1, tl = u & 31;
        xs[u] = xb[(size_t)(cc*FF + f0 + r)*TT + t0 + tl];
    }
    #pragma unroll
    for (int rep = 0; rep < 8; rep++) {
        int u = rep*128 + tid;
        int j = u >> 6, cc = u & 63;
        wpsp[cc*18 + j] = make_float2(psi_w[j*CC + cc], psi_w[(j+16)*CC + cc]);
        wphp[cc*18 + j] = make_float2(phi_w[j*CC + cc], phi_w[(j+16)*CC + cc]);
    }
    #pragma unroll
    for (int rep = 0; rep < 8; rep++) {
        int u = rep*128 + tid;
        int o = u >> 4, j = u & 15;
        Wwsp[o*18 + j] = make_float2(W_w[o*33 + j], W_w[o*33 + j + 16]);
    }
    if (tid < 64) {
        float acc = 0.f;
        #pragma unroll
        for (int i = 0; i < 32; i++) acc = fmaf(h0_w[i], theta_w[i*CC + tid], acc);
        uS[tid] = acc;
    } else if (tid == 64) {
        float acc = 0.f;
        #pragma unroll
        for (int i = 0; i < 32; i++) acc = fmaf(h0_w[i], theta_b[i], acc);
        tbS = acc;
    }
    __syncthreads();

    // register-blocked pooled conv: 2 j-pairs x 4 pool positions x 2 convs
    int ml = tid >> 3, ig = tid & 7;
    unsigned long long ap[8], af[8];
    #pragma unroll
    for (int i = 0; i < 8; i++) { ap[i] = 0ull; af[i] = 0ull; }
    const float2* wp0 = wpsp + ig*2;
    const float2* wf0 = wphp + ig*2;
    const float*  xr0 = xs + 2*ml;
    #pragma unroll 8
    for (int cc = 0; cc < 64; cc++) {
        ulonglong2 wP = *(const ulonglong2*)(wp0 + cc*18);
        ulonglong2 wF = *(const ulonglong2*)(wf0 + cc*18);
        float2 v0 = *(const float2*)(xr0 + cc*64);
        float2 v1 = *(const float2*)(xr0 + cc*64 + 32);
        unsigned long long d00 = dup2(v0.x), d01 = dup2(v0.y);
        unsigned long long d10 = dup2(v1.x), d11 = dup2(v1.y);
        ffma2(ap[0], wP.x, d00); ffma2(ap[1], wP.x, d01); ffma2(ap[2], wP.x, d10); ffma2(ap[3], wP.x, d11);
        ffma2(ap[4], wP.y, d00); ffma2(ap[5], wP.y, d01); ffma2(ap[6], wP.y, d10); ffma2(ap[7], wP.y, d11);
        ffma2(af[0], wF.x, d00); ffma2(af[1], wF.x, d01); ffma2(af[2], wF.x, d10); ffma2(af[3], wF.x, d11);
        ffma2(af[4], wF.y, d00); ffma2(af[5], wF.y, d01); ffma2(af[6], wF.y, d10); ffma2(af[7], wF.y, d11);
    }

    float qpart = 0.f;
    #pragma unroll
    for (int jj = 0; jj < 2; jj++) {
        int j = ig*2 + jj;
        float2 p0 = unpk(ap[jj*4+0]), p1 = unpk(ap[jj*4+1]);
        float2 p2 = unpk(ap[jj*4+2]), p3 = unpk(ap[jj*4+3]);
        float plo = fmaxf(fmaxf(p0.x,p1.x), fmaxf(p2.x,p3.x)) + psi_b[j];
        float phv = fmaxf(fmaxf(p0.y,p1.y), fmaxf(p2.y,p3.y)) + psi_b[j+16];
        psi_sp[ml*17 + j] = make_float2(plo, phv);
        float2 q0 = unpk(af[jj*4+0]), q1 = unpk(af[jj*4+1]);
        float2 q2 = unpk(af[jj*4+2]), q3 = unpk(af[jj*4+3]);
        float flo = fmaxf(fmaxf(q0.x,q1.x), fmaxf(q2.x,q3.x)) + phi_b[j];
        float fhi = fmaxf(fmaxf(q0.y,q1.y), fmaxf(q2.y,q3.y)) + phi_b[j+16];
        qpart = fmaf(h1_w[j], flo, qpart);
        qpart = fmaf(h1_w[j+16], fhi, qpart);
    }
    phi_part[ml*8 + ig] = qpart;

    // s[n] for the 64 n's this tile covers
    if (tid < 64) {
        int r_ = tid >> 5, tl = tid & 31;
        const float* xr = xs + r_*32 + tl;
        float s = tbS;
        #pragma unroll 16
        for (int cc = 0; cc < 64; cc++) s = fmaf(uS[cc], xr[cc*64], s);
        int fg = f0 + r_, tg = t0 + tl;
        s += h2_w[0]*((float)fg*(1.f/63.f)) + h2_w[1]*((float)tg*(1.f/127.f));
        g_s[b*NN + fg*TT + tg] = s;
    }
    __syncthreads();

    if (tid < 16) {
        const float* pp = phi_part + tid*8;
        float acc = ((pp[0]+pp[1]) + (pp[2]+pp[3])) + ((pp[4]+pp[5]) + (pp[6]+pp[7]));
        int tmm = tm0 + tid;
        float bp = h2_w[0]*((float)fm*(1.f/31.f)) + h2_w[1]*((float)tmm*(1.f/63.f));
        g_q[b*MM + fm*64 + tmm] = acc - bp;
    }

    // z[o][m] = sum_j W-pairs . psi-pairs
    const unsigned long long* Ww64 = (const unsigned long long*)Wwsp;
    const unsigned long long* Ps64 = (const unsigned long long*)psi_sp;
    float* zout = g_z + (size_t)b*CC*MM + fm*64 + tm0;
    #pragma unroll
    for (int rep = 0; rep < 8; rep++) {
        int task = rep*128 + tid;
        int o = task >> 4, mlz = task & 15;
        unsigned long long acc = 0ull;
        #pragma unroll
        for (int j = 0; j < 16; j++)
            ffma2(acc, Ww64[o*18 + j], Ps64[mlz*17 + j]);
        float2 rr = unpk(acc);
        zout[(size_t)o*MM + mlz] = rr.x + rr.y;
    }
}

// ---------------------------------------------------------------------------
// K2: per-batch bitonic sort of q, then all N binary searches. grid 4, block 1024.
// ---------------------------------------------------------------------------
__global__ __launch_bounds__(1024) void k2_sort_search()
{
    __shared__ unsigned long long sm[MM];
    __shared__ float keyF[MM];
    int b = blockIdx.x;
    int t = threadIdx.x;
    int lane = t & 31;
    int e0 = (t >> 5)*64 + lane*2;
    int e1 = e0 + 1;

    cudaGridDependencySynchronize();

    float2 f01 = *(const float2*)(g_q + b*MM + e0);
    unsigned u0 = __float_as_uint(f01.x); u0 ^= ((int)u0 < 0 ? 0xFFFFFFFFu : 0x80000000u);
    unsigned u1 = __float_as_uint(f01.y); u1 ^= ((int)u1 < 0 ? 0xFFFFFFFFu : 0x80000000u);
    unsigned long long a = ((unsigned long long)u0 << 32) | (unsigned)e0;
    unsigned long long c = ((unsigned long long)u1 << 32) | (unsigned)e1;

    #pragma unroll 1
    for (int k = 2; k <= MM; k <<= 1) {
        #pragma unroll 1
        for (int j = k >> 1; j > 0; j >>= 1) {
            if (j >= 64) {
                __syncthreads();
                sm[e0] = a; sm[e1] = c;
                __syncthreads();
                unsigned long long pa = sm[e0 ^ j];
                unsigned long long pc = sm[e1 ^ j];
                bool keepmin = (((e0 & j) == 0) == ((e0 & k) == 0));
                a = keepmin ? (a < pa ? a : pa) : (a < pa ? pa : a);
                c = keepmin ? (c < pc ? c : pc) : (c < pc ? pc : c);
            } else if (j >= 2) {
                int msk = j >> 1;
                unsigned long long pa = __shfl_xor_sync(0xFFFFFFFFu, a, msk);
                unsigned long long pc = __shfl_xor_sync(0xFFFFFFFFu, c, msk);
                bool keepmin = (((lane & msk) == 0) == ((e0 & k) == 0));
                a = keepmin ? (a < pa ? a : pa) : (a < pa ? pa : a);
                c = keepmin ? (c < pc ? c : pc) : (c < pc ? pc : c);
            } else {
                bool up = ((e0 & k) == 0);
                unsigned long long mn = (a < c ? a : c), mx = (a < c ? c : a);
                a = up ? mn : mx;
                c = up ? mx : mn;
            }
        }
    }
    {
        unsigned k0 = (unsigned)(a >> 32); k0 ^= ((int)k0 < 0 ? 0x80000000u : 0xFFFFFFFFu);
        unsigned k1v = (unsigned)(c >> 32); k1v ^= ((int)k1v < 0 ? 0x80000000u : 0xFFFFFFFFu);
        float fa = __uint_as_float(k0), fc = __uint_as_float(k1v);
        keyF[e0] = fa; keyF[e1] = fc;
        g_qs[b*MM + e0] = fa; g_qs[b*MM + e1] = fc;
        g_perm[b*MM + e0] = (int)(unsigned)(a & 0xFFFFFFFFull);
        g_perm[b*MM + e1] = (int)(unsigned)(c & 0xFFFFFFFFull);
    }
    __syncthreads();

    #pragma unroll
    for (int r = 0; r < 8; r++) {
        int n = r*1024 + t;
        float keyv = -g_s[b*NN + n];
        int lo = 0, hi = MM;
        while (lo < hi) { int mid = (lo + hi) >> 1; if (keyF[mid] > keyv) hi = mid; else lo = mid + 1; }
        g_k[b*NN + n] = lo;
    }
}

// ---------------------------------------------------------------------------
// K3: suffix sums pre-scaled by As[o]; PQ layout [b][o][k] -> coalesced stores.
// grid 256 (= B*C), block 256.
// ---------------------------------------------------------------------------
__global__ __launch_bounds__(256) void k3_scan(
    const float* __restrict__ bn_g, const float* __restrict__ bn_v)
{
    __shared__ float zS[MM];
    __shared__ float qsS[MM];
    __shared__ int   pS[MM];
    __shared__ float wtP[8], wtQ[8];

    int bo = blockIdx.x;
    int b = bo >> 6, o = bo & 63;
    int t = threadIdx.x, lane = t & 31, w = t >> 5;

    float As = bn_g[o]*rsqrtf(bn_v[o] + EPSF)*(1.0f/(float)MM);

    cudaGridDependencySynchronize();

    const float* zrow = g_z + ((size_t)b*CC + o)*MM;
    #pragma unroll
    for (int rep = 0; rep < 8; rep++) {
        int i = rep*256 + t;
        zS[i] = zrow[i]; qsS[i] = g_qs[b*MM + i]; pS[i] = g_perm[b*MM + i];
    }
    __syncthreads();

    float vP[8], vQ[8];
    int base = t*8;
    float sp = 0.f, sq = 0.f;
    #pragma unroll
    for (int e = 7; e >= 0; e--) {
        float zv = zS[pS[base + e]];
        sp += zv; sq = fmaf(qsS[base + e], zv, sq);
        vP[e] = sp; vQ[e] = sq;
    }
    float isp = sp, isq = sq;
    #pragma unroll
    for (int d = 1; d < 32; d <<= 1) {
        float tp = __shfl_down_sync(0xFFFFFFFFu, isp, d);
        float tq = __shfl_down_sync(0xFFFFFFFFu, isq, d);
        if (lane + d < 32) { isp += tp; isq += tq; }
    }
    if (lane == 0) { wtP[w] = isp; wtQ[w] = isq; }
    __syncthreads();
    float offP = isp - sp, offQ = isq - sq;
    #pragma unroll
    for (int w2 = 0; w2 < 8; w2++) if (w2 > w) { offP += wtP[w2]; offQ += wtQ[w2]; }

    float2* outp = g_PQ + ((size_t)b*CC + o)*(MM+1);
    #pragma unroll
    for (int e = 0; e < 8; e++)
        outp[base + e] = make_float2((vP[e]+offP)*As, (vQ[e]+offQ)*As);
    if (t == 0) outp[MM] = make_float2(0.f, 0.f);
}

// ---------------------------------------------------------------------------
// K4: per (b, o-pair, n-half): PQ rows in smem, streamed coalesced epilogue.
// grid 256, block 256, smem ~32.8KB.
// ---------------------------------------------------------------------------
__global__ __launch_bounds__(256) void k4_apply(
    const float* __restrict__ x, const float* __restrict__ W_b,
    const float* __restrict__ bn_g, const float* __restrict__ bn_b,
    const float* __restrict__ bn_m, const float* __restrict__ bn_v,
    float* __restrict__ out)
{
    __shared__ __align__(16) float2 rowA[MM+1];
    __shared__ __align__(16) float2 rowB[MM+1];

    int tid = threadIdx.x;
    int bid = blockIdx.x;
    int b = bid >> 6;
    int rem = bid & 63;
    int opair = rem >> 1, nh = rem & 1;
    int o0 = opair*2, o1 = o0 + 1;

    float inv0 = bn_g[o0]*rsqrtf(bn_v[o0] + EPSF);
    float inv1 = bn_g[o1]*rsqrtf(bn_v[o1] + EPSF);
    float DsA = fmaf(W_b[o0], inv0, bn_b[o0] - bn_m[o0]*inv0);
    float DsB = fmaf(W_b[o1], inv1, bn_b[o1] - bn_m[o1]*inv1);

    cudaGridDependencySynchronize();

    const float2* PQa = g_PQ + ((size_t)b*CC + o0)*(MM+1);
    const float2* PQb = g_PQ + ((size_t)b*CC + o1)*(MM+1);
    #pragma unroll
    for (int rep = 0; rep < 9; rep++) {
        int i = rep*256 + tid;
        if (i <= MM) { rowA[i] = PQa[i]; rowB[i] = PQb[i]; }
    }
    __syncthreads();

    int nbase = nh*4096;
    const float* sb = g_s + b*NN;
    const int*   kb = g_k + b*NN;
    const float* xA = x   + ((size_t)b*CC + o0)*NN;
    const float* xB = x   + ((size_t)b*CC + o1)*NN;
    float*       oA = out + ((size_t)b*CC + o0)*NN;
    float*       oB = out + ((size_t)b*CC + o1)*NN;

    #pragma unroll
    for (int it = 0; it < 8; it++) {
        int n = nbase + (it*256 + tid)*2;
        float2 s2 = *(const float2*)(sb + n);
        int2   kv = *(const int2*)(kb + n);
        float2 xa = *(const float2*)(xA + n);
        float2 xb2 = *(const float2*)(xB + n);
        float2 a0 = rowA[kv.x], a1 = rowA[kv.y];
        float2 b0 = rowB[kv.x], b1 = rowB[kv.y];
        float2 ra, rb;
        ra.x = fmaf(s2.x, a0.x, a0.y) + DsA + xa.x;
        ra.y = fmaf(s2.y, a1.x, a1.y) + DsA + xa.y;
        rb.x = fmaf(s2.x, b0.x, b0.y) + DsB + xb2.x;
        rb.y = fmaf(s2.y, b1.x, b1.y) + DsB + xb2.y;
        *(float2*)(oA + n) = ra;
        *(float2*)(oB + n) = rb;
    }
}

// ---------------------------------------------------------------------------
extern "C" void kernel_launch(void* const* d_in, const int* in_sizes, int n_in,
                              void* d_out, int out_size)
{
    const float* x       = (const float*)d_in[0];
    const float* psi_w   = (const float*)d_in[1];
    const float* psi_b   = (const float*)d_in[2];
    const float* theta_w = (const float*)d_in[3];
    const float* theta_b = (const float*)d_in[4];
    const float* phi_w   = (const float*)d_in[5];
    const float* phi_b   = (const float*)d_in[6];
    const float* h0_w    = (const float*)d_in[7];
    const float* h1_w    = (const float*)d_in[8];
    const float* h2_w    = (const float*)d_in[9];
    const float* W_w     = (const float*)d_in[10];
    const float* W_b     = (const float*)d_in[11];
    const float* bn_g    = (const float*)d_in[12];
    const float* bn_b    = (const float*)d_in[13];
    const float* bn_m    = (const float*)d_in[14];
    const float* bn_v    = (const float*)d_in[15];
    float* out = (float*)d_out;

    k1_zq<<<512, 128>>>(x, psi_w, psi_b, theta_w, theta_b, phi_w, phi_b,
                        h0_w, h1_w, h2_w, W_w);

    cudaLaunchAttribute attr[1];
    attr[0].id = cudaLaunchAttributeProgrammaticStreamSerialization;
    attr[0].val.programmaticStreamSerializationAllowed = 1;

    {
        cudaLaunchConfig_t cfg = {};
        cfg.gridDim = dim3(4); cfg.blockDim = dim3(1024);
        cfg.attrs = attr; cfg.numAttrs = 1;
        cudaLaunchKernelEx(&cfg, k2_sort_search);
    }
    {
        cudaLaunchConfig_t cfg = {};
        cfg.gridDim = dim3(256); cfg.blockDim = dim3(256);
        cfg.attrs = attr; cfg.numAttrs = 1;
        cudaLaunchKernelEx(&cfg, k3_scan, bn_g, bn_v);
    }
    {
        cudaLaunchConfig_t cfg = {};
        cfg.gridDim = dim3(256); cfg.blockDim = dim3(256);
        cfg.attrs = attr; cfg.numAttrs = 1;
        cudaLaunchKernelEx(&cfg, k4_apply, x, W_b, bn_g, bn_b, bn_m, bn_v, out);
    }
}

// round 8
// speedup vs baseline: 1.9642x; 1.4361x over previous
#include <cuda_runtime.h>
#include <cuda_bf16.h>
#include <cstdint>

#define BB 4
#define CC 64
#define FF 64
#define TT 128
#define IC 32
#define NN 8192
#define MM 2048
#define EPSF 1e-5f

// Scratch (device globals; allocation forbidden)
__device__ float  g_q[BB*MM];
__device__ float  g_qs[BB*MM];
__device__ int    g_perm[BB*MM];
__device__ float  g_z[BB*CC*MM];
__device__ float  g_s[BB*NN];
__device__ int    g_k[BB*NN];
__device__ float2 g_PQ[BB*CC*(MM+1)];   // [b][o][k]: (P,Q) suffix sums, pre-scaled

__device__ __forceinline__ void ffma2(unsigned long long &d, unsigned long long a, unsigned long long b) {
    asm("fma.rn.f32x2 %0, %1, %2, %0;" : "+l"(d) : "l"(a), "l"(b));
}
__device__ __forceinline__ unsigned long long dup2(float v) {
    unsigned long long r; asm("mov.b64 %0, {%1, %1};" : "=l"(r) : "f"(v)); return r;
}
__device__ __forceinline__ float2 unpk(unsigned long long v) {
    float2 r; asm("mov.b64 {%0, %1}, %2;" : "=f"(r.x), "=f"(r.y) : "l"(v)); return r;
}

// ---------------------------------------------------------------------------
// K1: pooled psi/phi convs -> q[b,m], z[b,o,m]; also s[b,n] (theta folded).
// grid 512 (= B * 128 tiles of 16 m), block 128.
// ---------------------------------------------------------------------------
__global__ __launch_bounds__(128) void k1_zq(
    const float* __restrict__ x,
    const float* __restrict__ psi_w, const float* __restrict__ psi_b,
    const float* __restrict__ theta_w, const float* __restrict__ theta_b,
    const float* __restrict__ phi_w, const float* __restrict__ phi_b,
    const float* __restrict__ h0_w, const float* __restrict__ h1_w,
    const float* __restrict__ h2_w, const float* __restrict__ W_w)
{
    __shared__ __align__(16) float  xs[64*2*32];       // [c][r][tl]
    __shared__ __align__(16) float2 wpsp[64*18];       // [c][j] pairs (j, j+16)
    __shared__ __align__(16) float2 wphp[64*18];
    __shared__ __align__(16) float2 Wwsp[64*18];       // [o][j] pairs
    __shared__ __align__(16) float2 psi_sp[16*17];     // [ml][j] pairs
    __shared__ float phi_part[16*8];
    __shared__ float uS[64];
    __shared__ float tbS;

    int tid = threadIdx.x;
    int bid = blockIdx.x;
    int b   = bid >> 7;
    int g   = bid & 127;
    int fm  = g >> 2;
    int tm0 = (g & 3) << 4;
    int f0 = fm << 1;
    int t0 = tm0 << 1;

    const float* xb = x + (size_t)b*CC*NN;
    #pragma unroll
    for (int rep = 0; rep < 32; rep++) {
        int u = rep*128 + tid;
        int cc = u >> 6, r = (u >> 5) & 1, tl = u & 31;
        xs[u] = xb[(size_t)(cc*FF + f0 + r)*TT + t0 + tl];
    }
    #pragma unroll
    for (int rep = 0; rep < 8; rep++) {
        int u = rep*128 + tid;
        int j = u >> 6, cc = u & 63;
        wpsp[cc*18 + j] = make_float2(psi_w[j*CC + cc], psi_w[(j+16)*CC + cc]);
        wphp[cc*18 + j] = make_float2(phi_w[j*CC + cc], phi_w[(j+16)*CC + cc]);
    }
    #pragma unroll
    for (int rep = 0; rep < 8; rep++) {
        int u = rep*128 + tid;
        int o = u >> 4, j = u & 15;
        Wwsp[o*18 + j] = make_float2(W_w[o*33 + j], W_w[o*33 + j + 16]);
    }
    if (tid < 64) {
        float acc = 0.f;
        #pragma unroll
        for (int i = 0; i < 32; i++) acc = fmaf(h0_w[i], theta_w[i*CC + tid], acc);
        uS[tid] = acc;
    } else if (tid == 64) {
        float acc = 0.f;
        #pragma unroll
        for (int i = 0; i < 32; i++) acc = fmaf(h0_w[i], theta_b[i], acc);
        tbS = acc;
    }
    __syncthreads();

    // register-blocked pooled conv: 2 j-pairs x 4 pool positions x 2 convs
    int ml = tid >> 3, ig = tid & 7;
    unsigned long long ap[8], af[8];
    #pragma unroll
    for (int i = 0; i < 8; i++) { ap[i] = 0ull; af[i] = 0ull; }
    const float2* wp0 = wpsp + ig*2;
    const float2* wf0 = wphp + ig*2;
    const float*  xr0 = xs + 2*ml;
    #pragma unroll 8
    for (int cc = 0; cc < 64; cc++) {
        ulonglong2 wP = *(const ulonglong2*)(wp0 + cc*18);
        ulonglong2 wF = *(const ulonglong2*)(wf0 + cc*18);
        float2 v0 = *(const float2*)(xr0 + cc*64);
        float2 v1 = *(const float2*)(xr0 + cc*64 + 32);
        unsigned long long d00 = dup2(v0.x), d01 = dup2(v0.y);
        unsigned long long d10 = dup2(v1.x), d11 = dup2(v1.y);
        ffma2(ap[0], wP.x, d00); ffma2(ap[1], wP.x, d01); ffma2(ap[2], wP.x, d10); ffma2(ap[3], wP.x, d11);
        ffma2(ap[4], wP.y, d00); ffma2(ap[5], wP.y, d01); ffma2(ap[6], wP.y, d10); ffma2(ap[7], wP.y, d11);
        ffma2(af[0], wF.x, d00); ffma2(af[1], wF.x, d01); ffma2(af[2], wF.x, d10); ffma2(af[3], wF.x, d11);
        ffma2(af[4], wF.y, d00); ffma2(af[5], wF.y, d01); ffma2(af[6], wF.y, d10); ffma2(af[7], wF.y, d11);
    }

    float qpart = 0.f;
    #pragma unroll
    for (int jj = 0; jj < 2; jj++) {
        int j = ig*2 + jj;
        float2 p0 = unpk(ap[jj*4+0]), p1 = unpk(ap[jj*4+1]);
        float2 p2 = unpk(ap[jj*4+2]), p3 = unpk(ap[jj*4+3]);
        float plo = fmaxf(fmaxf(p0.x,p1.x), fmaxf(p2.x,p3.x)) + psi_b[j];
        float phv = fmaxf(fmaxf(p0.y,p1.y), fmaxf(p2.y,p3.y)) + psi_b[j+16];
        psi_sp[ml*17 + j] = make_float2(plo, phv);
        float2 q0 = unpk(af[jj*4+0]), q1 = unpk(af[jj*4+1]);
        float2 q2 = unpk(af[jj*4+2]), q3 = unpk(af[jj*4+3]);
        float flo = fmaxf(fmaxf(q0.x,q1.x), fmaxf(q2.x,q3.x)) + phi_b[j];
        float fhi = fmaxf(fmaxf(q0.y,q1.y), fmaxf(q2.y,q3.y)) + phi_b[j+16];
        qpart = fmaf(h1_w[j], flo, qpart);
        qpart = fmaf(h1_w[j+16], fhi, qpart);
    }
    phi_part[ml*8 + ig] = qpart;

    // s[n] for the 64 n's this tile covers
    if (tid < 64) {
        int r_ = tid >> 5, tl = tid & 31;
        const float* xr = xs + r_*32 + tl;
        float s = tbS;
        #pragma unroll 16
        for (int cc = 0; cc < 64; cc++) s = fmaf(uS[cc], xr[cc*64], s);
        int fg = f0 + r_, tg = t0 + tl;
        s += h2_w[0]*((float)fg*(1.f/63.f)) + h2_w[1]*((float)tg*(1.f/127.f));
        g_s[b*NN + fg*TT + tg] = s;
    }
    __syncthreads();

    if (tid < 16) {
        const float* pp = phi_part + tid*8;
        float acc = ((pp[0]+pp[1]) + (pp[2]+pp[3])) + ((pp[4]+pp[5]) + (pp[6]+pp[7]));
        int tmm = tm0 + tid;
        float bp = h2_w[0]*((float)fm*(1.f/31.f)) + h2_w[1]*((float)tmm*(1.f/63.f));
        g_q[b*MM + fm*64 + tmm] = acc - bp;
    }

    // z[o][m] = sum_j W-pairs . psi-pairs
    const unsigned long long* Ww64 = (const unsigned long long*)Wwsp;
    const unsigned long long* Ps64 = (const unsigned long long*)psi_sp;
    float* zout = g_z + (size_t)b*CC*MM + fm*64 + tm0;
    #pragma unroll
    for (int rep = 0; rep < 8; rep++) {
        int task = rep*128 + tid;
        int o = task >> 4, mlz = task & 15;
        unsigned long long acc = 0ull;
        #pragma unroll
        for (int j = 0; j < 16; j++)
            ffma2(acc, Ww64[o*18 + j], Ps64[mlz*17 + j]);
        float2 rr = unpk(acc);
        zout[(size_t)o*MM + mlz] = rr.x + rr.y;
    }
}

// ---------------------------------------------------------------------------
// K2: parallel rank-sort of q. grid 128 (= B*32 segments of 64 elems), block 256.
// rank[m] = #{j : (key_j, j) < (key_m, m)}  -> unique permutation, scatter.
// Each thread: 1 owned element x 512-key segment (via uint4), 4-lane reduce.
// ---------------------------------------------------------------------------
__global__ __launch_bounds__(256) void k2_rank()
{
    __shared__ __align__(16) unsigned ordS[MM];
    __shared__ float qfS[MM];
    int bid = blockIdx.x;
    int b   = bid >> 5;
    int seg = bid & 31;        // owns elements [seg*64, seg*64+64)
    int tid = threadIdx.x;

    cudaGridDependencySynchronize();

    #pragma unroll
    for (int rep = 0; rep < 8; rep++) {
        int i = rep*256 + tid;
        float f = g_q[b*MM + i];
        unsigned u = __float_as_uint(f);
        u ^= (((int)u) < 0) ? 0xFFFFFFFFu : 0x80000000u;
        ordS[i] = u; qfS[i] = f;
    }
    __syncthreads();

    int el = tid >> 2;          // 0..63
    int part = tid & 3;         // segment of 512 keys
    int e = seg*64 + el;
    unsigned ki = ordS[e];
    int cnt = 0;
    const uint4* basep = (const uint4*)(ordS + part*512);
    #pragma unroll 8
    for (int i = 0; i < 128; i++) {
        uint4 v = basep[i];
        int j0 = part*512 + i*4;
        cnt += (int)(v.x < ki) | ((v.x == ki) & (j0+0 < e));
        cnt += (int)(v.y < ki) | ((v.y == ki) & (j0+1 < e));
        cnt += (int)(v.z < ki) | ((v.z == ki) & (j0+2 < e));
        cnt += (int)(v.w < ki) | ((v.w == ki) & (j0+3 < e));
    }
    cnt += __shfl_down_sync(0xFFFFFFFFu, cnt, 2);
    cnt += __shfl_down_sync(0xFFFFFFFFu, cnt, 1);
    if (part == 0) {
        g_qs[b*MM + cnt] = qfS[e];
        g_perm[b*MM + cnt] = e;
    }
}

// ---------------------------------------------------------------------------
// K3: suffix sums pre-scaled by As[o] (coalesced [b][o][k] stores) + the
// binary searches for this block's n-chunk (qsS already resident).
// grid 256 (= B*C), block 256.
// ---------------------------------------------------------------------------
__global__ __launch_bounds__(256) void k3_scan(
    const float* __restrict__ bn_g, const float* __restrict__ bn_v)
{
    __shared__ float zS[MM];
    __shared__ float qsS[MM];
    __shared__ int   pS[MM];
    __shared__ float wtP[8], wtQ[8];

    int bo = blockIdx.x;
    int b = bo >> 6, o = bo & 63;
    int t = threadIdx.x, lane = t & 31, w = t >> 5;

    float As = bn_g[o]*rsqrtf(bn_v[o] + EPSF)*(1.0f/(float)MM);

    cudaGridDependencySynchronize();

    const float* zrow = g_z + ((size_t)b*CC + o)*MM;
    #pragma unroll
    for (int rep = 0; rep < 8; rep++) {
        int i = rep*256 + t;
        zS[i] = zrow[i]; qsS[i] = g_qs[b*MM + i]; pS[i] = g_perm[b*MM + i];
    }
    __syncthreads();

    // binary searches for n-chunk [o*128, o*128+128): first k with qs[k] > -s
    if (t < 128) {
        int n = o*128 + t;
        float keyv = -g_s[b*NN + n];
        int lo = 0, hi = MM;
        while (lo < hi) { int mid = (lo + hi) >> 1; if (qsS[mid] > keyv) hi = mid; else lo = mid + 1; }
        g_k[b*NN + n] = lo;
    }

    float vP[8], vQ[8];
    int base = t*8;
    float sp = 0.f, sq = 0.f;
    #pragma unroll
    for (int e = 7; e >= 0; e--) {
        float zv = zS[pS[base + e]];
        sp += zv; sq = fmaf(qsS[base + e], zv, sq);
        vP[e] = sp; vQ[e] = sq;
    }
    float isp = sp, isq = sq;
    #pragma unroll
    for (int d = 1; d < 32; d <<= 1) {
        float tp = __shfl_down_sync(0xFFFFFFFFu, isp, d);
        float tq = __shfl_down_sync(0xFFFFFFFFu, isq, d);
        if (lane + d < 32) { isp += tp; isq += tq; }
    }
    if (lane == 0) { wtP[w] = isp; wtQ[w] = isq; }
    __syncthreads();
    float offP = isp - sp, offQ = isq - sq;
    #pragma unroll
    for (int w2 = 0; w2 < 8; w2++) if (w2 > w) { offP += wtP[w2]; offQ += wtQ[w2]; }

    float2* outp = g_PQ + ((size_t)b*CC + o)*(MM+1);
    #pragma unroll
    for (int e = 0; e < 8; e++)
        outp[base + e] = make_float2((vP[e]+offP)*As, (vQ[e]+offQ)*As);
    if (t == 0) outp[MM] = make_float2(0.f, 0.f);
}

// ---------------------------------------------------------------------------
// K4: per (b, o-pair, n-quarter): PQ rows in smem, streamed coalesced epilogue.
// grid 512, block 256, smem ~32.8KB.
// ---------------------------------------------------------------------------
__global__ __launch_bounds__(256) void k4_apply(
    const float* __restrict__ x, const float* __restrict__ W_b,
    const float* __restrict__ bn_g, const float* __restrict__ bn_b,
    const float* __restrict__ bn_m, const float* __restrict__ bn_v,
    float* __restrict__ out)
{
    __shared__ __align__(16) float2 rowA[MM+1];
    __shared__ __align__(16) float2 rowB[MM+1];

    int tid = threadIdx.x;
    int bid = blockIdx.x;
    int b = bid >> 7;
    int rem = bid & 127;
    int opair = rem >> 2, nq = rem & 3;
    int o0 = opair*2, o1 = o0 + 1;

    float inv0 = bn_g[o0]*rsqrtf(bn_v[o0] + EPSF);
    float inv1 = bn_g[o1]*rsqrtf(bn_v[o1] + EPSF);
    float DsA = fmaf(W_b[o0], inv0, bn_b[o0] - bn_m[o0]*inv0);
    float DsB = fmaf(W_b[o1], inv1, bn_b[o1] - bn_m[o1]*inv1);

    cudaGridDependencySynchronize();

    const float2* PQa = g_PQ + ((size_t)b*CC + o0)*(MM+1);
    const float2* PQb = g_PQ + ((size_t)b*CC + o1)*(MM+1);
    #pragma unroll
    for (int rep = 0; rep < 9; rep++) {
        int i = rep*256 + tid;
        if (i <= MM) { rowA[i] = PQa[i]; rowB[i] = PQb[i]; }
    }
    __syncthreads();

    int nbase = nq*2048;
    const float* sb = g_s + b*NN;
    const int*   kb = g_k + b*NN;
    const float* xA = x   + ((size_t)b*CC + o0)*NN;
    const float* xB = x   + ((size_t)b*CC + o1)*NN;
    float*       oA = out + ((size_t)b*CC + o0)*NN;
    float*       oB = out + ((size_t)b*CC + o1)*NN;

    #pragma unroll
    for (int it = 0; it < 4; it++) {
        int n = nbase + (it*256 + tid)*2;
        float2 s2 = *(const float2*)(sb + n);
        int2   kv = *(const int2*)(kb + n);
        float2 xa = *(const float2*)(xA + n);
        float2 xb2 = *(const float2*)(xB + n);
        float2 a0 = rowA[kv.x], a1 = rowA[kv.y];
        float2 b0 = rowB[kv.x], b1 = rowB[kv.y];
        float2 ra, rb;
        ra.x = fmaf(s2.x, a0.x, a0.y) + DsA + xa.x;
        ra.y = fmaf(s2.y, a1.x, a1.y) + DsA + xa.y;
        rb.x = fmaf(s2.x, b0.x, b0.y) + DsB + xb2.x;
        rb.y = fmaf(s2.y, b1.x, b1.y) + DsB + xb2.y;
        *(float2*)(oA + n) = ra;
        *(float2*)(oB + n) = rb;
    }
}

// ---------------------------------------------------------------------------
extern "C" void kernel_launch(void* const* d_in, const int* in_sizes, int n_in,
                              void* d_out, int out_size)
{
    const float* x       = (const float*)d_in[0];
    const float* psi_w   = (const float*)d_in[1];
    const float* psi_b   = (const float*)d_in[2];
    const float* theta_w = (const float*)d_in[3];
    const float* theta_b = (const float*)d_in[4];
    const float* phi_w   = (const float*)d_in[5];
    const float* phi_b   = (const float*)d_in[6];
    const float* h0_w    = (const float*)d_in[7];
    const float* h1_w    = (const float*)d_in[8];
    const float* h2_w    = (const float*)d_in[9];
    const float* W_w     = (const float*)d_in[10];
    const float* W_b     = (const float*)d_in[11];
    const float* bn_g    = (const float*)d_in[12];
    const float* bn_b    = (const float*)d_in[13];
    const float* bn_m    = (const float*)d_in[14];
    const float* bn_v    = (const float*)d_in[15];
    float* out = (float*)d_out;

    k1_zq<<<512, 128>>>(x, psi_w, psi_b, theta_w, theta_b, phi_w, phi_b,
                        h0_w, h1_w, h2_w, W_w);

    cudaLaunchAttribute attr[1];
    attr[0].id = cudaLaunchAttributeProgrammaticStreamSerialization;
    attr[0].val.programmaticStreamSerializationAllowed = 1;

    {
        cudaLaunchConfig_t cfg = {};
        cfg.gridDim = dim3(128); cfg.blockDim = dim3(256);
        cfg.attrs = attr; cfg.numAttrs = 1;
        cudaLaunchKernelEx(&cfg, k2_rank);
    }
    {
        cudaLaunchConfig_t cfg = {};
        cfg.gridDim = dim3(256); cfg.blockDim = dim3(256);
        cfg.attrs = attr; cfg.numAttrs = 1;
        cudaLaunchKernelEx(&cfg, k3_scan, bn_g, bn_v);
    }
    {
        cudaLaunchConfig_t cfg = {};
        cfg.gridDim = dim3(512); cfg.blockDim = dim3(256);
        cfg.attrs = attr; cfg.numAttrs = 1;
        cudaLaunchKernelEx(&cfg, k4_apply, x, W_b, bn_g, bn_b, bn_m, bn_v, out);
    }
}

// round 10
// speedup vs baseline: 2.0756x; 1.0567x over previous
#include <cuda_runtime.h>
#include <cuda_bf16.h>
#include <cstdint>

#define BB 4
#define CC 64
#define FF 64
#define TT 128
#define IC 32
#define NN 8192
#define MM 2048
#define EPSF 1e-5f

// Scratch (device globals; allocation forbidden)
__device__ float  g_q[BB*MM];
__device__ float  g_qs[BB*MM];
__device__ int    g_perm[BB*MM];
__device__ float  g_z[BB*CC*MM];
__device__ float  g_s[BB*NN];
__device__ float2 g_sk[BB*NN];            // (s[n], bitcast k[n])
__device__ float2 g_PQ[BB*CC*(MM+2)];     // [b][o][k] padded to 16B-aligned rows

__device__ __forceinline__ void ffma2(unsigned long long &d, unsigned long long a, unsigned long long b) {
    asm("fma.rn.f32x2 %0, %1, %2, %0;" : "+l"(d) : "l"(a), "l"(b));
}
__device__ __forceinline__ unsigned long long dup2(float v) {
    unsigned long long r; asm("mov.b64 %0, {%1, %1};" : "=l"(r) : "f"(v)); return r;
}
__device__ __forceinline__ float2 unpk(unsigned long long v) {
    float2 r; asm("mov.b64 {%0, %1}, %2;" : "=f"(r.x), "=f"(r.y) : "l"(v)); return r;
}

// ---------------------------------------------------------------------------
// K1: pooled psi/phi convs -> q[b,m], z[b,o,m]; also s[b,n] (theta folded).
// grid 512 (= B * 128 tiles of 16 m), block 128.
// ---------------------------------------------------------------------------
__global__ __launch_bounds__(128) void k1_zq(
    const float* __restrict__ x,
    const float* __restrict__ psi_w, const float* __restrict__ psi_b,
    const float* __restrict__ theta_w, const float* __restrict__ theta_b,
    const float* __restrict__ phi_w, const float* __restrict__ phi_b,
    const float* __restrict__ h0_w, const float* __restrict__ h1_w,
    const float* __restrict__ h2_w, const float* __restrict__ W_w)
{
    __shared__ __align__(16) float  xs[64*2*32];       // [c][r][tl]
    __shared__ __align__(16) float2 wpsp[64*18];       // [c][j] pairs (j, j+16)
    __shared__ __align__(16) float2 wphp[64*18];
    __shared__ __align__(16) float2 Wwsp[64*18];       // [o][j] pairs
    __shared__ __align__(16) float2 psi_sp[16*17];     // [ml][j] pairs
    __shared__ float phi_part[16*8];
    __shared__ float uS[64];
    __shared__ float tbS;

    int tid = threadIdx.x;
    int bid = blockIdx.x;
    int b   = bid >> 7;
    int g   = bid & 127;
    int fm  = g >> 2;
    int tm0 = (g & 3) << 4;
    int f0 = fm << 1;
    int t0 = tm0 << 1;

    const float* xb = x + (size_t)b*CC*NN;
    const float4* xb4 = (const float4*)xb;
    float4* xs4 = (float4*)xs;
    // 1024 float4 total: cc (64) x r (2) x tl4 (8)
    #pragma unroll
    for (int rep = 0; rep < 8; rep++) {
        int u = rep*128 + tid;
        int cc = u >> 4, r = (u >> 3) & 1, tl4 = u & 7;
        xs4[u] = xb4[(cc*FF + f0 + r)*32 + (t0 >> 2) + tl4];
    }
    #pragma unroll
    for (int rep = 0; rep < 8; rep++) {
        int u = rep*128 + tid;
        int j = u >> 6, cc = u & 63;
        wpsp[cc*18 + j] = make_float2(psi_w[j*CC + cc], psi_w[(j+16)*CC + cc]);
        wphp[cc*18 + j] = make_float2(phi_w[j*CC + cc], phi_w[(j+16)*CC + cc]);
    }
    #pragma unroll
    for (int rep = 0; rep < 8; rep++) {
        int u = rep*128 + tid;
        int o = u >> 4, j = u & 15;
        Wwsp[o*18 + j] = make_float2(W_w[o*33 + j], W_w[o*33 + j + 16]);
    }
    if (tid < 64) {
        float acc = 0.f;
        #pragma unroll
        for (int i = 0; i < 32; i++) acc = fmaf(h0_w[i], theta_w[i*CC + tid], acc);
        uS[tid] = acc;
    } else if (tid == 64) {
        float acc = 0.f;
        #pragma unroll
        for (int i = 0; i < 32; i++) acc = fmaf(h0_w[i], theta_b[i], acc);
        tbS = acc;
    }
    __syncthreads();

    // register-blocked pooled conv: 2 j-pairs x 4 pool positions x 2 convs
    int ml = tid >> 3, ig = tid & 7;
    unsigned long long ap[8], af[8];
    #pragma unroll
    for (int i = 0; i < 8; i++) { ap[i] = 0ull; af[i] = 0ull; }
    const float2* wp0 = wpsp + ig*2;
    const float2* wf0 = wphp + ig*2;
    const float*  xr0 = xs + 2*ml;
    #pragma unroll 8
    for (int cc = 0; cc < 64; cc++) {
        ulonglong2 wP = *(const ulonglong2*)(wp0 + cc*18);
        ulonglong2 wF = *(const ulonglong2*)(wf0 + cc*18);
        float2 v0 = *(const float2*)(xr0 + cc*64);
        float2 v1 = *(const float2*)(xr0 + cc*64 + 32);
        unsigned long long d00 = dup2(v0.x), d01 = dup2(v0.y);
        unsigned long long d10 = dup2(v1.x), d11 = dup2(v1.y);
        ffma2(ap[0], wP.x, d00); ffma2(ap[1], wP.x, d01); ffma2(ap[2], wP.x, d10); ffma2(ap[3], wP.x, d11);
        ffma2(ap[4], wP.y, d00); ffma2(ap[5], wP.y, d01); ffma2(ap[6], wP.y, d10); ffma2(ap[7], wP.y, d11);
        ffma2(af[0], wF.x, d00); ffma2(af[1], wF.x, d01); ffma2(af[2], wF.x, d10); ffma2(af[3], wF.x, d11);
        ffma2(af[4], wF.y, d00); ffma2(af[5], wF.y, d01); ffma2(af[6], wF.y, d10); ffma2(af[7], wF.y, d11);
    }

    float qpart = 0.f;
    #pragma unroll
    for (int jj = 0; jj < 2; jj++) {
        int j = ig*2 + jj;
        float2 p0 = unpk(ap[jj*4+0]), p1 = unpk(ap[jj*4+1]);
        float2 p2 = unpk(ap[jj*4+2]), p3 = unpk(ap[jj*4+3]);
        float plo = fmaxf(fmaxf(p0.x,p1.x), fmaxf(p2.x,p3.x)) + psi_b[j];
        float phv = fmaxf(fmaxf(p0.y,p1.y), fmaxf(p2.y,p3.y)) + psi_b[j+16];
        psi_sp[ml*17 + j] = make_float2(plo, phv);
        float2 q0 = unpk(af[jj*4+0]), q1 = unpk(af[jj*4+1]);
        float2 q2 = unpk(af[jj*4+2]), q3 = unpk(af[jj*4+3]);
        float flo = fmaxf(fmaxf(q0.x,q1.x), fmaxf(q2.x,q3.x)) + phi_b[j];
        float fhi = fmaxf(fmaxf(q0.y,q1.y), fmaxf(q2.y,q3.y)) + phi_b[j+16];
        qpart = fmaf(h1_w[j], flo, qpart);
        qpart = fmaf(h1_w[j+16], fhi, qpart);
    }
    phi_part[ml*8 + ig] = qpart;

    // s[n] for the 64 n's this tile covers
    if (tid < 64) {
        int r_ = tid >> 5, tl = tid & 31;
        const float* xr = xs + r_*32 + tl;
        float s = tbS;
        #pragma unroll 16
        for (int cc = 0; cc < 64; cc++) s = fmaf(uS[cc], xr[cc*64], s);
        int fg = f0 + r_, tg = t0 + tl;
        s += h2_w[0]*((float)fg*(1.f/63.f)) + h2_w[1]*((float)tg*(1.f/127.f));
        g_s[b*NN + fg*TT + tg] = s;
    }
    __syncthreads();

    if (tid < 16) {
        const float* pp = phi_part + tid*8;
        float acc = ((pp[0]+pp[1]) + (pp[2]+pp[3])) + ((pp[4]+pp[5]) + (pp[6]+pp[7]));
        int tmm = tm0 + tid;
        float bp = h2_w[0]*((float)fm*(1.f/31.f)) + h2_w[1]*((float)tmm*(1.f/63.f));
        g_q[b*MM + fm*64 + tmm] = acc - bp;
    }

    // z[o][m] = sum_j W-pairs . psi-pairs
    const unsigned long long* Ww64 = (const unsigned long long*)Wwsp;
    const unsigned long long* Ps64 = (const unsigned long long*)psi_sp;
    float* zout = g_z + (size_t)b*CC*MM + fm*64 + tm0;
    #pragma unroll
    for (int rep = 0; rep < 8; rep++) {
        int task = rep*128 + tid;
        int o = task >> 4, mlz = task & 15;
        unsigned long long acc = 0ull;
        #pragma unroll
        for (int j = 0; j < 16; j++)
            ffma2(acc, Ww64[o*18 + j], Ps64[mlz*17 + j]);
        float2 rr = unpk(acc);
        zout[(size_t)o*MM + mlz] = rr.x + rr.y;
    }
}

// ---------------------------------------------------------------------------
// K2: parallel rank-sort of q. grid 128 (= B*32 segments of 64 elems), block 256.
// ---------------------------------------------------------------------------
__global__ __launch_bounds__(256) void k2_rank()
{
    __shared__ __align__(16) unsigned ordS[MM];
    __shared__ float qfS[MM];
    int bid = blockIdx.x;
    int b   = bid >> 5;
    int seg = bid & 31;
    int tid = threadIdx.x;

    cudaGridDependencySynchronize();

    #pragma unroll
    for (int rep = 0; rep < 8; rep++) {
        int i = rep*256 + tid;
        float f = g_q[b*MM + i];
        unsigned u = __float_as_uint(f);
        u ^= (((int)u) < 0) ? 0xFFFFFFFFu : 0x80000000u;
        ordS[i] = u; qfS[i] = f;
    }
    __syncthreads();

    int el = tid >> 2;
    int part = tid & 3;
    int e = seg*64 + el;
    unsigned ki = ordS[e];
    int cnt = 0;
    const uint4* basep = (const uint4*)(ordS + part*512);
    #pragma unroll 8
    for (int i = 0; i < 128; i++) {
        uint4 v = basep[i];
        int j0 = part*512 + i*4;
        cnt += (int)(v.x < ki) | ((v.x == ki) & (j0+0 < e));
        cnt += (int)(v.y < ki) | ((v.y == ki) & (j0+1 < e));
        cnt += (int)(v.z < ki) | ((v.z == ki) & (j0+2 < e));
        cnt += (int)(v.w < ki) | ((v.w == ki) & (j0+3 < e));
    }
    cnt += __shfl_down_sync(0xFFFFFFFFu, cnt, 2);
    cnt += __shfl_down_sync(0xFFFFFFFFu, cnt, 1);
    if (part == 0) {
        g_qs[b*MM + cnt] = qfS[e];
        g_perm[b*MM + cnt] = e;
    }
}

// ---------------------------------------------------------------------------
// K3: suffix sums pre-scaled by As[o] (coalesced [b][o][k] stores) + binary
// searches for this block's n-chunk, packed into g_sk.
// grid 256 (= B*C), block 256.
// ---------------------------------------------------------------------------
__global__ __launch_bounds__(256) void k3_scan(
    const float* __restrict__ bn_g, const float* __restrict__ bn_v)
{
    __shared__ float zS[MM];
    __shared__ float qsS[MM];
    __shared__ int   pS[MM];
    __shared__ float wtP[8], wtQ[8];

    int bo = blockIdx.x;
    int b = bo >> 6, o = bo & 63;
    int t = threadIdx.x, lane = t & 31, w = t >> 5;

    float As = bn_g[o]*rsqrtf(bn_v[o] + EPSF)*(1.0f/(float)MM);

    cudaGridDependencySynchronize();

    const float* zrow = g_z + ((size_t)b*CC + o)*MM;
    #pragma unroll
    for (int rep = 0; rep < 8; rep++) {
        int i = rep*256 + t;
        zS[i] = zrow[i]; qsS[i] = g_qs[b*MM + i]; pS[i] = g_perm[b*MM + i];
    }
    __syncthreads();

    // binary searches for n-chunk [o*128, o*128+128): first k with qs[k] > -s
    if (t < 128) {
        int n = o*128 + t;
        float sv = g_s[b*NN + n];
        float keyv = -sv;
        int lo = 0, hi = MM;
        while (lo < hi) { int mid = (lo + hi) >> 1; if (qsS[mid] > keyv) hi = mid; else lo = mid + 1; }
        g_sk[b*NN + n] = make_float2(sv, __int_as_float(lo));
    }

    float vP[8], vQ[8];
    int base = t*8;
    float sp = 0.f, sq = 0.f;
    #pragma unroll
    for (int e = 7; e >= 0; e--) {
        float zv = zS[pS[base + e]];
        sp += zv; sq = fmaf(qsS[base + e], zv, sq);
        vP[e] = sp; vQ[e] = sq;
    }
    float isp = sp, isq = sq;
    #pragma unroll
    for (int d = 1; d < 32; d <<= 1) {
        float tp = __shfl_down_sync(0xFFFFFFFFu, isp, d);
        float tq = __shfl_down_sync(0xFFFFFFFFu, isq, d);
        if (lane + d < 32) { isp += tp; isq += tq; }
    }
    if (lane == 0) { wtP[w] = isp; wtQ[w] = isq; }
    __syncthreads();
    float offP = isp - sp, offQ = isq - sq;
    #pragma unroll
    for (int w2 = 0; w2 < 8; w2++) if (w2 > w) { offP += wtP[w2]; offQ += wtQ[w2]; }

    float2* outp = g_PQ + ((size_t)b*CC + o)*(MM+2);
    #pragma unroll
    for (int e = 0; e < 8; e++)
        outp[base + e] = make_float2((vP[e]+offP)*As, (vQ[e]+offQ)*As);
    if (t == 0) { outp[MM] = make_float2(0.f, 0.f); outp[MM+1] = make_float2(0.f, 0.f); }
}

// ---------------------------------------------------------------------------
// K4: per (b, o): stage PQ row once, full-n float4 streamed epilogue.
// grid 256, block 256, smem 16.4KB.
// ---------------------------------------------------------------------------
__global__ __launch_bounds__(256) void k4_apply(
    const float* __restrict__ x, const float* __restrict__ W_b,
    const float* __restrict__ bn_g, const float* __restrict__ bn_b,
    const float* __restrict__ bn_m, const float* __restrict__ bn_v,
    float* __restrict__ out)
{
    __shared__ __align__(16) float2 row[MM+2];

    int tid = threadIdx.x;
    int bid = blockIdx.x;
    int b = bid >> 6;
    int o = bid & 63;

    float inv = bn_g[o]*rsqrtf(bn_v[o] + EPSF);
    float Ds = fmaf(W_b[o], inv, bn_b[o] - bn_m[o]*inv);

    cudaGridDependencySynchronize();

    const float4* PQ4 = (const float4*)(g_PQ + ((size_t)b*CC + o)*(MM+2));
    float4* row4 = (float4*)row;
    #pragma unroll
    for (int rep = 0; rep < 4; rep++) row4[rep*256 + tid] = PQ4[rep*256 + tid];
    if (tid == 0) row4[1024] = PQ4[1024];
    __syncthreads();

    const float4* sk4 = (const float4*)(g_sk + (size_t)b*NN);
    const float4* x4  = (const float4*)(x   + ((size_t)b*CC + o)*NN);
    float4*       o4  = (float4*)(out + ((size_t)b*CC + o)*NN);

    #pragma unroll
    for (int it = 0; it < 8; it++) {
        int idx = it*256 + tid;                 // group of 4 n
        float4 xa  = x4[idx];
        float4 skA = sk4[idx*2];
        float4 skB = sk4[idx*2 + 1];
        float2 r0 = row[__float_as_int(skA.y)];
        float2 r1 = row[__float_as_int(skA.w)];
        float2 r2 = row[__float_as_int(skB.y)];
        float2 r3 = row[__float_as_int(skB.w)];
        float4 r;
        r.x = fmaf(skA.x, r0.x, r0.y) + Ds + xa.x;
        r.y = fmaf(skA.z, r1.x, r1.y) + Ds + xa.y;
        r.z = fmaf(skB.x, r2.x, r2.y) + Ds + xa.z;
        r.w = fmaf(skB.z, r3.x, r3.y) + Ds + xa.w;
        o4[idx] = r;
    }
}

// ---------------------------------------------------------------------------
extern "C" void kernel_launch(void* const* d_in, const int* in_sizes, int n_in,
                              void* d_out, int out_size)
{
    const float* x       = (const float*)d_in[0];
    const float* psi_w   = (const float*)d_in[1];
    const float* psi_b   = (const float*)d_in[2];
    const float* theta_w = (const float*)d_in[3];
    const float* theta_b = (const float*)d_in[4];
    const float* phi_w   = (const float*)d_in[5];
    const float* phi_b   = (const float*)d_in[6];
    const float* h0_w    = (const float*)d_in[7];
    const float* h1_w    = (const float*)d_in[8];
    const float* h2_w    = (const float*)d_in[9];
    const float* W_w     = (const float*)d_in[10];
    const float* W_b     = (const float*)d_in[11];
    const float* bn_g    = (const float*)d_in[12];
    const float* bn_b    = (const float*)d_in[13];
    const float* bn_m    = (const float*)d_in[14];
    const float* bn_v    = (const float*)d_in[15];
    float* out = (float*)d_out;

    k1_zq<<<512, 128>>>(x, psi_w, psi_b, theta_w, theta_b, phi_w, phi_b,
                        h0_w, h1_w, h2_w, W_w);

    cudaLaunchAttribute attr[1];
    attr[0].id = cudaLaunchAttributeProgrammaticStreamSerialization;
    attr[0].val.programmaticStreamSerializationAllowed = 1;

    {
        cudaLaunchConfig_t cfg = {};
        cfg.gridDim = dim3(128); cfg.blockDim = dim3(256);
        cfg.attrs = attr; cfg.numAttrs = 1;
        cudaLaunchKernelEx(&cfg, k2_rank);
    }
    {
        cudaLaunchConfig_t cfg = {};
        cfg.gridDim = dim3(256); cfg.blockDim = dim3(256);
        cfg.attrs = attr; cfg.numAttrs = 1;
        cudaLaunchKernelEx(&cfg, k3_scan, bn_g, bn_v);
    }
    {
        cudaLaunchConfig_t cfg = {};
        cfg.gridDim = dim3(256); cfg.blockDim = dim3(256);
        cfg.attrs = attr; cfg.numAttrs = 1;
        cudaLaunchKernelEx(&cfg, k4_apply, x, W_b, bn_g, bn_b, bn_m, bn_v, out);
    }
}